// round 17
// baseline (speedup 1.0000x reference)
#include <cuda_runtime.h>
#include <cuda_fp16.h>

#define NN 50000
#define EE 800000
#define FULL 0xffffffffu
#define SHIFT 30.0f

// ---------------- device scratch ----------------
__device__ __align__(16) __half g_bufT[NN * 128];  // messages, fp16
__device__ __align__(16) float  g_bufX[NN * 128];  // layer activations (fp32)
__device__ float  g_dinv[NN];
__device__ int    g_cnt[NN];
__device__ int    g_off[NN];
__device__ int    g_cur[NN];
__device__ int    g_tot;
__device__ int    g_es[EE];          // CSR: src ids grouped by dst
__device__ float2 g_Sv[NN];          // per-node per-head <g, a_src>
__device__ float2 g_Dv[NN];          // per-node per-head <g, a_dst>
__device__ float2 g_eb[EE];          // cached per-edge exp(score-SHIFT) (2 heads)

// ---------------- helpers ----------------
__device__ __forceinline__ float lrelu(float x) { return x > 0.f ? x : 0.2f * x; }

// fp16 gather: 1 LDG.128 (8 halves) + 4 HFMA2, no converts
__device__ __forceinline__ void acc8h(const uint4* __restrict__ base, size_t idx,
                                      __half2 w, __half2* acc) {
    uint4 q = __ldg(base + idx);
    __half2* h = (__half2*)&q;
#pragma unroll
    for (int k = 0; k < 4; k++) acc[k] = __hfma2(h[k], w, acc[k]);
}
__device__ __forceinline__ void h2tof8(const __half2* acc, float* f) {
#pragma unroll
    for (int k = 0; k < 4; k++) {
        float2 t = __half22float2(acc[k]);
        f[2 * k] = t.x;
        f[2 * k + 1] = t.y;
    }
}

__device__ __forceinline__ void mma16816(float* c, unsigned a0, unsigned a1,
                                         unsigned a2, unsigned a3,
                                         unsigned b0, unsigned b1) {
    asm volatile(
        "mma.sync.aligned.m16n8k16.row.col.f32.f16.f16.f32 "
        "{%0,%1,%2,%3}, {%4,%5,%6,%7}, {%8,%9}, {%0,%1,%2,%3};"
        : "+f"(c[0]), "+f"(c[1]), "+f"(c[2]), "+f"(c[3])
        : "r"(a0), "r"(a1), "r"(a2), "r"(a3), "r"(b0), "r"(b1));
}

// ---------------- CSR build ----------------
__global__ void k_cnt_zero(int n) {
    int i = blockIdx.x * blockDim.x + threadIdx.x;
    if (i == 0) g_tot = 0;
    if (i < n) g_cnt[i] = 0;
}
__global__ void k_hist(const int* __restrict__ dst, int e) {
    int i = blockIdx.x * blockDim.x + threadIdx.x;
    if (i < e) atomicAdd(&g_cnt[dst[i]], 1);
}
__global__ void k_off(int n) {
    int i = blockIdx.x * blockDim.x + threadIdx.x;
    if (i >= n) return;
    int c = g_cnt[i];
    int p = atomicAdd(&g_tot, c);
    g_off[i] = p;
    g_cur[i] = p;
    g_dinv[i] = rsqrtf((float)(c + 1));
}
__global__ void k_fill(const int* __restrict__ src, const int* __restrict__ dst, int e) {
    int i = blockIdx.x * blockDim.x + threadIdx.x;
    if (i >= e) return;
    int d = dst[i];
    int p = atomicAdd(&g_cur[d], 1);
    g_es[p] = src[i];
}

// ---------------- tensor-core GEMM (m16n8k16 HMMA): Y = X @ W, fp16 out ------------
template <int K, int J, int SD, bool SCALE>
__global__ __launch_bounds__(256)
void k_gemm(const float* __restrict__ X, const float* __restrict__ W,
            __half* __restrict__ Y, const float* __restrict__ asv,
            const float* __restrict__ adv, int n) {
    constexpr int SA = K + 8;           // padded half stride
    constexpr int JT = J / 64;
    extern __shared__ char smem[];
    __half* As = (__half*)smem;                          // [128][SA]
    __half* Wt = (__half*)(smem + 128 * SA * 2);         // [J][SA] (W transposed)
    float*  Cs = (float*)smem;                           // [128][J], aliases As/Wt

    int tid = threadIdx.x;
    int wid = tid >> 5, l = tid & 31;
    int gid = l >> 2, tig = l & 3;
    int row0 = blockIdx.x * 128;

    const int HK = K / 2;
    for (int idx = tid; idx < 128 * HK; idx += 256) {
        int r = idx / HK, c2 = idx % HK;
        int gr = row0 + r;
        float2 v = (gr < n) ? ((const float2*)X)[(size_t)gr * HK + c2]
                            : make_float2(0.f, 0.f);
        *(__half2*)&As[r * SA + c2 * 2] = __floats2half2_rn(v.x, v.y);
    }
    for (int idx = tid; idx < K * J; idx += 256) {
        int k = idx / J, j = idx % J;
        Wt[j * SA + k] = __float2half_rn(W[idx]);
    }
    __syncthreads();

    float cfr[J / 8][4];
#pragma unroll
    for (int jt = 0; jt < J / 8; jt++)
#pragma unroll
        for (int c = 0; c < 4; c++) cfr[jt][c] = 0.f;

    const __half* Ar = As + (wid * 16) * SA;
#pragma unroll
    for (int k0 = 0; k0 < K; k0 += 16) {
        unsigned a0 = *(const unsigned*)&Ar[gid * SA + k0 + tig * 2];
        unsigned a1 = *(const unsigned*)&Ar[(gid + 8) * SA + k0 + tig * 2];
        unsigned a2 = *(const unsigned*)&Ar[gid * SA + k0 + 8 + tig * 2];
        unsigned a3 = *(const unsigned*)&Ar[(gid + 8) * SA + k0 + 8 + tig * 2];
#pragma unroll
        for (int jt = 0; jt < J / 8; jt++) {
            unsigned b0 = *(const unsigned*)&Wt[(jt * 8 + gid) * SA + k0 + tig * 2];
            unsigned b1 = *(const unsigned*)&Wt[(jt * 8 + gid) * SA + k0 + 8 + tig * 2];
            mma16816(cfr[jt], a0, a1, a2, a3, b0, b1);
        }
    }
    __syncthreads();

#pragma unroll
    for (int jt = 0; jt < J / 8; jt++) {
        int r = wid * 16 + gid;
        *(float2*)&Cs[r * J + jt * 8 + tig * 2] = make_float2(cfr[jt][0], cfr[jt][1]);
        *(float2*)&Cs[(r + 8) * J + jt * 8 + tig * 2] = make_float2(cfr[jt][2], cfr[jt][3]);
    }
    __syncthreads();

    int tx = tid & 15, ty = tid >> 4;
    float acc[JT][8][4];
#pragma unroll
    for (int jc = 0; jc < JT; jc++)
#pragma unroll
        for (int i = 0; i < 8; i++)
            *(float4*)acc[jc][i] = *(const float4*)&Cs[(ty * 8 + i) * J + jc * 64 + tx * 4];

#pragma unroll
    for (int i = 0; i < 8; i++) {
        int gr = row0 + ty * 8 + i;
        if (gr >= n) continue;
        float dd = SCALE ? g_dinv[gr] : 1.f;
#pragma unroll
        for (int jc = 0; jc < JT; jc++) {
            __half2 p0 = __floats2half2_rn(dd * acc[jc][i][0], dd * acc[jc][i][1]);
            __half2 p1 = __floats2half2_rn(dd * acc[jc][i][2], dd * acc[jc][i][3]);
            uint2 st;
            st.x = *(unsigned*)&p0;
            st.y = *(unsigned*)&p1;
            ((uint2*)Y)[(size_t)gr * (J / 4) + jc * 16 + tx] = st;
        }
    }

    if (SD == 1) {
        float as[2][4], ad[2][4];
#pragma unroll
        for (int jc = 0; jc < JT; jc++)
#pragma unroll
            for (int c = 0; c < 4; c++) {
                as[jc][c] = asv[jc * 64 + tx * 4 + c];
                ad[jc][c] = adv[jc * 64 + tx * 4 + c];
            }
#pragma unroll
        for (int i = 0; i < 8; i++) {
            float s0 = 0.f, d0 = 0.f, s1 = 0.f, d1 = 0.f;
#pragma unroll
            for (int c = 0; c < 4; c++) {
                s0 += acc[0][i][c] * as[0][c];
                d0 += acc[0][i][c] * ad[0][c];
                s1 += acc[JT - 1][i][c] * as[1][c];
                d1 += acc[JT - 1][i][c] * ad[1][c];
            }
#pragma unroll
            for (int o = 8; o; o >>= 1) {
                s0 += __shfl_xor_sync(FULL, s0, o);
                d0 += __shfl_xor_sync(FULL, d0, o);
                s1 += __shfl_xor_sync(FULL, s1, o);
                d1 += __shfl_xor_sync(FULL, d1, o);
            }
            int gr = row0 + ty * 8 + i;
            if (tx == 0 && gr < n) {
                g_Sv[gr] = make_float2(s0, s1);
                g_Dv[gr] = make_float2(d0, d1);
            }
        }
    } else if (SD == 2) {
        float as[4], ad[4];
        int h = tx >> 3;
#pragma unroll
        for (int c = 0; c < 4; c++) {
            as[c] = asv[h * 32 + (tx & 7) * 4 + c];
            ad[c] = adv[h * 32 + (tx & 7) * 4 + c];
        }
#pragma unroll
        for (int i = 0; i < 8; i++) {
            float s = 0.f, d = 0.f;
#pragma unroll
            for (int c = 0; c < 4; c++) {
                s += acc[0][i][c] * as[c];
                d += acc[0][i][c] * ad[c];
            }
#pragma unroll
            for (int o = 4; o; o >>= 1) {
                s += __shfl_xor_sync(FULL, s, o);
                d += __shfl_xor_sync(FULL, d, o);
            }
            int gr = row0 + ty * 8 + i;
            if ((tx & 7) == 0 && gr < n) {
                ((float*)g_Sv)[gr * 2 + h] = s;
                ((float*)g_Dv)[gr * 2 + h] = d;
            }
        }
    }
}

// ---------------- GCN: 8 lanes/node, fp16 rows (1 LDG.128/lane/edge, no cvt) -------
template <bool PRESCALED>
__global__ __launch_bounds__(128)
void k_gcn_node(const __half* __restrict__ T, const float* __restrict__ b,
                float* __restrict__ X, int n) {
    int g = blockIdx.x * blockDim.x + threadIdx.x;
    int w = g >> 3;
    int lane = threadIdx.x & 7;
    unsigned gmask = 0xFFu << ((threadIdx.x & 31) & ~7);
    if (w >= n) return;   // subgroup exits together
    const uint4* T4 = (const uint4*)T;   // row = 64 halves = 8 uint4
    float dw = g_dinv[w];
    const __half2 ONE2 = __float2half2_rn(1.f);
    __half2 acch[4];
#pragma unroll
    for (int i = 0; i < 4; i++) acch[i] = __float2half2_rn(0.f);
    acc8h(T4, (size_t)w * 8 + lane, PRESCALED ? ONE2 : __float2half2_rn(dw), acch);
    int beg = g_off[w], end = beg + g_cnt[w];
    for (int base = beg; base < end; base += 8) {
        int j = base + lane;
        int sj = w;
        unsigned cpk = 0;
        if (j < end) {
            sj = g_es[j];
            if (!PRESCALED) {
                __half2 c2 = __float2half2_rn(g_dinv[sj]);
                cpk = *(unsigned*)&c2;
            }
        }
        int cnt = min(8, end - base);
        for (int t = 0; t < cnt; t++) {
            int s = __shfl_sync(gmask, sj, t, 8);
            __half2 c2v = ONE2;
            if (!PRESCALED) {
                unsigned cc = __shfl_sync(gmask, cpk, t, 8);
                c2v = *(__half2*)&cc;
            }
            acc8h(T4, (size_t)s * 8 + lane, c2v, acch);
        }
    }
    float acc[8];
    h2tof8(acch, acc);
    float bb[8];
    *(float4*)bb = ((const float4*)b)[lane * 2];
    *(float4*)(bb + 4) = ((const float4*)b)[lane * 2 + 1];
    float4 o0, o1;
    o0.x = fmaxf(dw * acc[0] + bb[0], 0.f);
    o0.y = fmaxf(dw * acc[1] + bb[1], 0.f);
    o0.z = fmaxf(dw * acc[2] + bb[2], 0.f);
    o0.w = fmaxf(dw * acc[3] + bb[3], 0.f);
    o1.x = fmaxf(dw * acc[4] + bb[4], 0.f);
    o1.y = fmaxf(dw * acc[5] + bb[5], 0.f);
    o1.z = fmaxf(dw * acc[6] + bb[6], 0.f);
    o1.w = fmaxf(dw * acc[7] + bb[7], 0.f);
    ((float4*)X)[(size_t)w * 16 + lane * 2] = o0;
    ((float4*)X)[(size_t)w * 16 + lane * 2 + 1] = o1;
}

// ---------------- fused GAT layer: SUBW lanes/node, fp16 rows ----------------------
// CH=64: SUBW=16 (block 256); CH=32: SUBW=8 (block 128). 8 channels per lane.
template <int CH, bool CONCAT>
__global__ void k_gat_node(const __half* __restrict__ T, const float* __restrict__ bias,
                           float* __restrict__ X, float* __restrict__ out, int n) {
    constexpr int SUBW = (CH == 64) ? 16 : 8;   // row = 2*CH halves = SUBW uint4
    int g = blockIdx.x * blockDim.x + threadIdx.x;
    int w = g / SUBW;
    int lane = threadIdx.x & (SUBW - 1);
    unsigned gmask = (SUBW == 16) ? (0xFFFFu << ((threadIdx.x & 31) & 16))
                                  : (0xFFu << ((threadIdx.x & 31) & ~7));
    if (w >= n) return;   // subgroup exits together
    float2 Dd = g_Dv[w];
    float2 Sw = g_Sv[w];
    float wself0 = __expf(lrelu(Sw.x + Dd.x) - SHIFT);
    float wself1 = __expf(lrelu(Sw.y + Dd.y) - SHIFT);
    int beg = g_off[w], end = beg + g_cnt[w];

    // --- pass 1: z = sum of exp(score - SHIFT); cache exp terms sequentially ---
    float z0 = (lane == 0) ? wself0 : 0.f;
    float z1 = (lane == 0) ? wself1 : 0.f;
    for (int j = beg + lane; j < end; j += SUBW) {
        float2 sv = g_Sv[g_es[j]];
        float w0 = __expf(lrelu(sv.x + Dd.x) - SHIFT);
        float w1 = __expf(lrelu(sv.y + Dd.y) - SHIFT);
        g_eb[j] = make_float2(w0, w1);
        z0 += w0;
        z1 += w1;
    }
#pragma unroll
    for (int o = SUBW / 2; o; o >>= 1) {
        z0 += __shfl_xor_sync(gmask, z0, o, SUBW);
        z1 += __shfl_xor_sync(gmask, z1, o, SUBW);
    }
    float iz0 = 1.f / z0;
    float iz1 = 1.f / z1;

    // --- pass 2: weighted feature accumulate; weights pre-packed as half2 ----------
    const uint4* T4 = (const uint4*)T;
    int hh = (lane >= SUBW / 2);
    __half2 acch[4];
#pragma unroll
    for (int i = 0; i < 4; i++) acch[i] = __float2half2_rn(0.f);
    float wself = hh ? wself1 * iz1 : wself0 * iz0;
    acc8h(T4, (size_t)w * SUBW + lane, __float2half2_rn(wself), acch);
    for (int base = beg; base < end; base += SUBW) {
        int j = base + lane;
        int sj = w;
        unsigned apk = 0;
        if (j < end) {
            sj = g_es[j];
            float2 eb = g_eb[j];
            __half2 ah = __halves2half2(__float2half_rn(eb.x * iz0),
                                        __float2half_rn(eb.y * iz1));
            apk = *(unsigned*)&ah;
        }
        int cnt = min(SUBW, end - base);
        for (int t = 0; t < cnt; t++) {
            int s = __shfl_sync(gmask, sj, t, SUBW);
            unsigned ap = __shfl_sync(gmask, apk, t, SUBW);
            __half2 a2 = *(__half2*)&ap;
            __half2 w2 = hh ? __high2half2(a2) : __low2half2(a2);
            acc8h(T4, (size_t)s * SUBW + lane, w2, acch);
        }
    }
    float acc[8];
    h2tof8(acch, acc);

    if (CONCAT) {
        float bb[8];
        *(float4*)bb = ((const float4*)bias)[lane * 2];
        *(float4*)(bb + 4) = ((const float4*)bias)[lane * 2 + 1];
        float4 o0, o1;
        o0.x = fmaxf(acc[0] + bb[0], 0.f);
        o0.y = fmaxf(acc[1] + bb[1], 0.f);
        o0.z = fmaxf(acc[2] + bb[2], 0.f);
        o0.w = fmaxf(acc[3] + bb[3], 0.f);
        o1.x = fmaxf(acc[4] + bb[4], 0.f);
        o1.y = fmaxf(acc[5] + bb[5], 0.f);
        o1.z = fmaxf(acc[6] + bb[6], 0.f);
        o1.w = fmaxf(acc[7] + bb[7], 0.f);
        ((float4*)X)[(size_t)w * 32 + lane * 2] = o0;
        ((float4*)X)[(size_t)w * 32 + lane * 2 + 1] = o1;
    } else {
        // SUBW=8: lanes 0-3 hold head0 ch[lane*8..+7]; lanes 4-7 head1 same channels.
        float v[8];
        int cl = lane & 3;
#pragma unroll
        for (int i = 0; i < 8; i++) {
            float oth = __shfl_sync(gmask, acc[i], cl + 4, 8);
            v[i] = 0.5f * (acc[i] + oth) + bias[cl * 8 + i];
        }
        float mx = v[0];
#pragma unroll
        for (int i = 1; i < 8; i++) mx = fmaxf(mx, v[i]);
        mx = fmaxf(mx, __shfl_xor_sync(gmask, mx, 1, 8));
        mx = fmaxf(mx, __shfl_xor_sync(gmask, mx, 2, 8));
        float sum = 0.f;
#pragma unroll
        for (int i = 0; i < 8; i++) sum += __expf(v[i] - mx);
        sum += __shfl_xor_sync(gmask, sum, 1, 8);
        sum += __shfl_xor_sync(gmask, sum, 2, 8);
        float ls = logf(sum);
        if (lane < 4) {
            float4 o0, o1;
            o0.x = v[0] - mx - ls; o0.y = v[1] - mx - ls;
            o0.z = v[2] - mx - ls; o0.w = v[3] - mx - ls;
            o1.x = v[4] - mx - ls; o1.y = v[5] - mx - ls;
            o1.z = v[6] - mx - ls; o1.w = v[7] - mx - ls;
            ((float4*)out)[(size_t)w * 8 + cl * 2] = o0;
            ((float4*)out)[(size_t)w * 8 + cl * 2 + 1] = o1;
        }
    }
}

// ---------------- launcher ----------------
static inline int cdiv(long long a, int b) { return (int)((a + b - 1) / b); }
static inline int gemm_smem(int K, int J) {
    int ab = 128 * (K + 8) * 2 + J * (K + 8) * 2;
    int cs = 128 * J * 4;
    return ab > cs ? ab : cs;
}

extern "C" void kernel_launch(void* const* d_in, const int* in_sizes, int n_in,
                              void* d_out, int out_size) {
    const float* x   = (const float*)d_in[0];
    const int*   ei  = (const int*)d_in[1];
    const float* W1  = (const float*)d_in[2];
    const float* b1  = (const float*)d_in[3];
    const float* W2  = (const float*)d_in[4];
    const float* b2  = (const float*)d_in[5];
    const float* Wg1 = (const float*)d_in[6];
    const float* as1 = (const float*)d_in[7];
    const float* ad1 = (const float*)d_in[8];
    const float* bg1 = (const float*)d_in[9];
    const float* Wg2 = (const float*)d_in[10];
    const float* as2 = (const float*)d_in[11];
    const float* ad2 = (const float*)d_in[12];
    const float* bg2 = (const float*)d_in[13];

    int n = in_sizes[0] / 128;
    int e = in_sizes[1] / 2;
    const int* src = ei;
    const int* dst = ei + e;

    __half* T = nullptr; cudaGetSymbolAddress((void**)&T, g_bufT);
    float*  X = nullptr; cudaGetSymbolAddress((void**)&X, g_bufX);
    float* out = (float*)d_out;

    static cudaStream_t s1 = nullptr;
    static cudaEvent_t e0 = nullptr, eCsr = nullptr;
    if (!s1) {
        cudaStreamCreateWithFlags(&s1, cudaStreamNonBlocking);
        cudaEventCreateWithFlags(&e0, cudaEventDisableTiming);
        cudaEventCreateWithFlags(&eCsr, cudaEventDisableTiming);
        cudaFuncSetAttribute(k_gemm<128, 64, 0, false>,
                             cudaFuncAttributeMaxDynamicSharedMemorySize, gemm_smem(128, 64));
        cudaFuncSetAttribute(k_gemm<64, 64, 0, true>,
                             cudaFuncAttributeMaxDynamicSharedMemorySize, gemm_smem(64, 64));
        cudaFuncSetAttribute(k_gemm<64, 128, 1, false>,
                             cudaFuncAttributeMaxDynamicSharedMemorySize, gemm_smem(64, 128));
        cudaFuncSetAttribute(k_gemm<128, 64, 2, false>,
                             cudaFuncAttributeMaxDynamicSharedMemorySize, gemm_smem(128, 64));
    }

    const int B = 256;
    int oct_blocks  = cdiv((long long)n * 8, 128);    // 3125 exact (block=128)
    int sw16_blocks = cdiv((long long)n * 16, 256);   // 3125 exact (block=256)
    int gemm_blocks = cdiv(n, 128);

    // --- fork: CSR build on side stream (overlapped with GEMM1) ---
    cudaEventRecord(e0, 0);
    cudaStreamWaitEvent(s1, e0, 0);
    k_cnt_zero<<<cdiv(n, B), B, 0, s1>>>(n);
    k_hist<<<cdiv(e, B), B, 0, s1>>>(dst, e);
    k_off<<<cdiv(n, B), B, 0, s1>>>(n);
    k_fill<<<cdiv(e, B), B, 0, s1>>>(src, dst, e);
    cudaEventRecord(eCsr, s1);

    // --- GCN1: 128 -> 64 (no dinv dependency; per-edge dinv in node kernel) ---
    k_gemm<128, 64, 0, false><<<gemm_blocks, 256, gemm_smem(128, 64)>>>(
        x, W1, T, nullptr, nullptr, n);
    cudaStreamWaitEvent(0, eCsr, 0);     // CSR + dinv ready before aggregation
    k_gcn_node<false><<<oct_blocks, 128>>>(T, b1, X, n);

    // --- GCN2: 64 -> 64 (rows pre-scaled by dinv; dinv already synced) ---
    k_gemm<64, 64, 0, true><<<gemm_blocks, 256, gemm_smem(64, 64)>>>(
        X, W2, T, nullptr, nullptr, n);
    k_gcn_node<true><<<oct_blocks, 128>>>(T, b2, X, n);

    // --- GAT1: 64 -> 2x64 concat (scores fused into GEMM epilogue) ---
    k_gemm<64, 128, 1, false><<<gemm_blocks, 256, gemm_smem(64, 128)>>>(
        X, Wg1, T, as1, ad1, n);
    k_gat_node<64, true><<<sw16_blocks, 256>>>(T, bg1, X, nullptr, n);

    // --- GAT2: 128 -> 2x32 mean + log_softmax ---
    k_gemm<128, 64, 2, false><<<gemm_blocks, 256, gemm_smem(128, 64)>>>(
        X, Wg2, T, as2, ad2, n);
    k_gat_node<32, false><<<oct_blocks, 128>>>(T, bg2, nullptr, out, n);
}